// round 3
// baseline (speedup 1.0000x reference)
#include <cuda_runtime.h>
#include <cuda_bf16.h>
#include <cstdint>
#include <cstddef>

#define B_ 2
#define T_ 2048
#define C_ 2048
#define H_ 16
#define D_ 128
#define EPS_ 1.1920929e-07f

typedef unsigned long long u64t;

// ---------------- f32x2 packed-FMA helpers (Blackwell FFMA2) ----------------
__device__ __forceinline__ u64t f2pack(float a, float b) {
    u64t r; asm("mov.b64 %0, {%1,%2};" : "=l"(r) : "f"(a), "f"(b)); return r;
}
__device__ __forceinline__ float2 f2unpack(u64t v) {
    float lo, hi; asm("mov.b64 {%0,%1}, %2;" : "=f"(lo), "=f"(hi) : "l"(v));
    return make_float2(lo, hi);
}
__device__ __forceinline__ void f2fma(u64t& d, u64t a, u64t b) {
    asm("fma.rn.f32x2 %0, %1, %2, %0;" : "+l"(d) : "l"(a), "l"(b));
}
__device__ __forceinline__ void f2mul(u64t& d, u64t a) {
    asm("mul.rn.f32x2 %0, %0, %1;" : "+l"(d) : "l"(a));
}

// ---------------- scratch (static device globals; no runtime alloc) ---------
__device__ float g_qkv[(size_t)B_ * T_ * 3 * C_];        // [B*T, 3C]
__device__ float g_q[(size_t)B_ * H_ * T_ * D_];         // [B*H, T, D]
__device__ float g_k[(size_t)B_ * H_ * T_ * D_];
__device__ float g_v[(size_t)B_ * H_ * T_ * D_];
__device__ float g_y[(size_t)B_ * T_ * C_];              // [B*T, C]
__device__ float g_cos[(size_t)T_ * D_];
__device__ float g_sin[(size_t)T_ * D_];

// ---------------- RoPE tables (double pow -> fp32, mirrors JAX rounding) ----
__global__ void rope_table_kernel(float* __restrict__ ct, float* __restrict__ st) {
    int idx = blockIdx.x * 256 + threadIdx.x;
    if (idx >= T_ * D_) return;
    int t = idx >> 7;
    int d = idx & 127;
    int j = d & 63;
    double inv = 1.0 / pow(1.0e6, (double)j / 64.0);
    float inv_f = (float)inv;
    float freq = (float)t * inv_f;     // fp32 product, same rounding as reference einsum
    ct[idx] = cosf(freq);
    st[idx] = sinf(freq);
}

// ---------------- SGEMM: C[M,N] = A[M,K] @ B[K,N], all row-major ------------
// 128x128 block tile, BK=8, 256 threads, 8x8 micro-tile, f32x2 accumulators.
__global__ __launch_bounds__(256, 2) void sgemm128_kernel(
    const float* __restrict__ A, const float* __restrict__ Bm,
    float* __restrict__ Cm, int M, int N, int K)
{
    __shared__ float As[8][128];   // transposed A tile
    __shared__ float Bs[8][128];

    const int tid = threadIdx.x;
    const int tx = tid & 15, ty = tid >> 4;
    const int row0 = blockIdx.y << 7;
    const int col0 = blockIdx.x << 7;

    const int arow = tid >> 1, acol = (tid & 1) << 2;
    const int brow = tid >> 5, bcol = (tid & 31) << 2;

    const float* Aptr = A + (size_t)(row0 + arow) * K + acol;
    const float* Bptr = Bm + (size_t)brow * N + col0 + bcol;

    u64t acc[8][4];
    #pragma unroll
    for (int i = 0; i < 8; i++)
        #pragma unroll
        for (int j = 0; j < 4; j++) acc[i][j] = 0ull;

    for (int k0 = 0; k0 < K; k0 += 8) {
        float4 av = *(const float4*)(Aptr + k0);
        float4 bv = *(const float4*)(Bptr + (size_t)k0 * N);
        As[acol + 0][arow] = av.x;
        As[acol + 1][arow] = av.y;
        As[acol + 2][arow] = av.z;
        As[acol + 3][arow] = av.w;
        *(float4*)&Bs[brow][bcol] = bv;
        __syncthreads();

        #pragma unroll
        for (int kk = 0; kk < 8; ++kk) {
            float4 a0 = *(const float4*)&As[kk][ty << 2];
            float4 a1 = *(const float4*)&As[kk][64 + (ty << 2)];
            float4 b0 = *(const float4*)&Bs[kk][tx << 2];
            float4 b1 = *(const float4*)&Bs[kk][64 + (tx << 2)];
            u64t pb0 = f2pack(b0.x, b0.y), pb1 = f2pack(b0.z, b0.w);
            u64t pb2 = f2pack(b1.x, b1.y), pb3 = f2pack(b1.z, b1.w);
            float aa[8] = {a0.x, a0.y, a0.z, a0.w, a1.x, a1.y, a1.z, a1.w};
            #pragma unroll
            for (int i = 0; i < 8; ++i) {
                u64t pa = f2pack(aa[i], aa[i]);
                f2fma(acc[i][0], pa, pb0);
                f2fma(acc[i][1], pa, pb1);
                f2fma(acc[i][2], pa, pb2);
                f2fma(acc[i][3], pa, pb3);
            }
        }
        __syncthreads();
    }

    #pragma unroll
    for (int i = 0; i < 8; ++i) {
        int r = (i < 4) ? ((ty << 2) + i) : (64 + (ty << 2) + i - 4);
        size_t co = (size_t)(row0 + r) * N + col0;
        float2 c0 = f2unpack(acc[i][0]), c1 = f2unpack(acc[i][1]);
        float2 c2 = f2unpack(acc[i][2]), c3 = f2unpack(acc[i][3]);
        float4 o0 = make_float4(c0.x, c0.y, c1.x, c1.y);
        float4 o1 = make_float4(c2.x, c2.y, c3.x, c3.y);
        *(float4*)&Cm[co + (tx << 2)] = o0;
        *(float4*)&Cm[co + 64 + (tx << 2)] = o1;
    }
}

// ---------------- fused per-head RMSNorm + RoPE + QKV split -----------------
// grid (H, T, B), 128 threads (one per d)
__global__ void qkv_post_kernel(
    const float* __restrict__ qkv,
    const float* __restrict__ qw, const float* __restrict__ kw,
    const float* __restrict__ ct, const float* __restrict__ st,
    float* __restrict__ Qo, float* __restrict__ Ko, float* __restrict__ Vo)
{
    const int h = blockIdx.x, t = blockIdx.y, b = blockIdx.z;
    const int d = threadIdx.x;
    const size_t base = ((size_t)(b * T_ + t)) * (3 * C_);

    float qv = qkv[base + h * D_ + d];
    float kv = qkv[base + C_ + h * D_ + d];
    float vv = qkv[base + 2 * C_ + h * D_ + d];

    __shared__ float sq[128], sk[128], red[8];

    float s2q = qv * qv, s2k = kv * kv;
    #pragma unroll
    for (int o = 16; o; o >>= 1) {
        s2q += __shfl_xor_sync(0xffffffffu, s2q, o);
        s2k += __shfl_xor_sync(0xffffffffu, s2k, o);
    }
    int w = d >> 5;
    if ((d & 31) == 0) { red[w] = s2q; red[4 + w] = s2k; }
    __syncthreads();
    float sumq = red[0] + red[1] + red[2] + red[3];
    float sumk = red[4] + red[5] + red[6] + red[7];
    float rq = rsqrtf(sumq * (1.0f / 128.0f) + EPS_) * qw[d];
    float rk = rsqrtf(sumk * (1.0f / 128.0f) + EPS_) * kw[d];
    sq[d] = qv * rq;
    sk[d] = kv * rk;
    __syncthreads();

    float c = ct[t * D_ + d], s = st[t * D_ + d];
    float qrot = (d < 64) ? -sq[d + 64] : sq[d - 64];
    float krot = (d < 64) ? -sk[d + 64] : sk[d - 64];
    float qo = sq[d] * c + qrot * s;
    float ko = sk[d] * c + krot * s;

    size_t oidx = (((size_t)(b * H_ + h)) * T_ + t) * D_ + d;
    Qo[oidx] = qo;
    Ko[oidx] = ko;
    Vo[oidx] = vv;
}

// ---------------- causal flash attention (fp32, f32x2 math) -----------------
// BQ = BK = 64, D = 128, 256 threads. grid (T/64, B*H)
#define FL_SMEM_FLOATS (8192 + 8448 + 8192 + 4160 + 192)
#define FL_SMEM_BYTES  (FL_SMEM_FLOATS * 4)

__global__ __launch_bounds__(256, 1) void flash_kernel(
    const float* __restrict__ Qg, const float* __restrict__ Kg,
    const float* __restrict__ Vg, float* __restrict__ Yg)
{
    extern __shared__ float sm[];
    float* Qs = sm;                         // [64][128]
    float* Ks = sm + 8192;                  // [64][132] (padded)
    float* Vs = sm + 8192 + 8448;           // [64][128]
    float* Ss = Vs + 8192;                  // [64][65]
    float* row_m = Ss + 4160;               // [64]
    float* row_l = row_m + 64;
    float* row_a = row_l + 64;

    const int tid = threadIdx.x;
    const int tx = tid & 15, ty = tid >> 4;
    const int bh = blockIdx.y;
    const int q0 = blockIdx.x << 6;

    const float* Qp = Qg + ((size_t)bh * T_ + q0) * D_;
    const float* Kp = Kg + (size_t)bh * T_ * D_;
    const float* Vp = Vg + (size_t)bh * T_ * D_;

    // load Q tile
    #pragma unroll
    for (int s = tid; s < 64 * 32; s += 256) {
        int r = s >> 5, c4 = (s & 31) << 2;
        *(float4*)&Qs[r * 128 + c4] = *(const float4*)&Qp[(size_t)r * D_ + c4];
    }
    if (tid < 64) { row_m[tid] = -3.0e38f; row_l[tid] = 0.0f; }

    u64t po[4][4];
    #pragma unroll
    for (int i = 0; i < 4; i++)
        #pragma unroll
        for (int j = 0; j < 4; j++) po[i][j] = 0ull;

    const int ktiles = (q0 >> 6) + 1;
    for (int kt = 0; kt < ktiles; ++kt) {
        const int k0 = kt << 6;
        __syncthreads();  // previous tile fully consumed (also covers Q load / init)

        #pragma unroll
        for (int s = tid; s < 64 * 32; s += 256) {
            int r = s >> 5, c4 = (s & 31) << 2;
            *(float4*)&Ks[r * 132 + c4] = *(const float4*)&Kp[((size_t)(k0 + r)) * D_ + c4];
            *(float4*)&Vs[r * 128 + c4] = *(const float4*)&Vp[((size_t)(k0 + r)) * D_ + c4];
        }
        __syncthreads();

        // ---- S = Q @ K^T (f32x2 packed over d) ----
        u64t ps[4][4];
        #pragma unroll
        for (int i = 0; i < 4; i++)
            #pragma unroll
            for (int j = 0; j < 4; j++) ps[i][j] = 0ull;

        #pragma unroll 4
        for (int dc = 0; dc < 32; ++dc) {
            ulonglong2 qv[4], kv[4];
            #pragma unroll
            for (int i = 0; i < 4; i++)
                qv[i] = *(const ulonglong2*)&Qs[(ty + 16 * i) * 128 + (dc << 2)];
            #pragma unroll
            for (int j = 0; j < 4; j++)
                kv[j] = *(const ulonglong2*)&Ks[(tx + 16 * j) * 132 + (dc << 2)];
            #pragma unroll
            for (int i = 0; i < 4; i++)
                #pragma unroll
                for (int j = 0; j < 4; j++) {
                    f2fma(ps[i][j], qv[i].x, kv[j].x);
                    f2fma(ps[i][j], qv[i].y, kv[j].y);
                }
        }

        // scale + causal mask + store to smem
        const bool diag = (k0 == q0);
        #pragma unroll
        for (int i = 0; i < 4; i++) {
            int ri = ty + 16 * i;
            #pragma unroll
            for (int j = 0; j < 4; j++) {
                int cj = tx + 16 * j;
                float2 f = f2unpack(ps[i][j]);
                float sv = (f.x + f.y) * (1.0f / 128.0f);
                if (diag && cj > ri) sv = -3.0e38f;
                Ss[ri * 65 + cj] = sv;
            }
        }
        __syncthreads();

        // ---- online softmax stats ----
        {
            int r = tid >> 2, c0 = (tid & 3) << 4;
            float mloc = -3.0e38f;
            #pragma unroll
            for (int jj = 0; jj < 16; jj++) mloc = fmaxf(mloc, Ss[r * 65 + c0 + jj]);
            mloc = fmaxf(mloc, __shfl_xor_sync(0xffffffffu, mloc, 1));
            mloc = fmaxf(mloc, __shfl_xor_sync(0xffffffffu, mloc, 2));
            if ((tid & 3) == 0) {
                float m_old = row_m[r];
                float m = fmaxf(m_old, mloc);
                float a = __expf(m_old - m);
                row_a[r] = a; row_m[r] = m; row_l[r] *= a;
            }
        }
        __syncthreads();
        {
            int r = tid >> 2, c0 = (tid & 3) << 4;
            float m = row_m[r], sum = 0.0f;
            #pragma unroll
            for (int jj = 0; jj < 16; jj++) {
                float p = __expf(Ss[r * 65 + c0 + jj] - m);
                Ss[r * 65 + c0 + jj] = p;
                sum += p;
            }
            sum += __shfl_xor_sync(0xffffffffu, sum, 1);
            sum += __shfl_xor_sync(0xffffffffu, sum, 2);
            if ((tid & 3) == 0) row_l[r] += sum;
        }
        __syncthreads();

        // ---- rescale O, then O += P @ V ----
        #pragma unroll
        for (int i = 0; i < 4; i++) {
            float a = row_a[ty + 16 * i];
            u64t pa = f2pack(a, a);
            #pragma unroll
            for (int jp = 0; jp < 4; jp++) f2mul(po[i][jp], pa);
        }

        #pragma unroll 4
        for (int kk = 0; kk < 64; ++kk) {
            ulonglong2 v0 = *(const ulonglong2*)&Vs[kk * 128 + (tx << 2)];
            ulonglong2 v1 = *(const ulonglong2*)&Vs[kk * 128 + 64 + (tx << 2)];
            #pragma unroll
            for (int i = 0; i < 4; i++) {
                float p = Ss[(ty + 16 * i) * 65 + kk];
                u64t pp = f2pack(p, p);
                f2fma(po[i][0], pp, v0.x);
                f2fma(po[i][1], pp, v0.y);
                f2fma(po[i][2], pp, v1.x);
                f2fma(po[i][3], pp, v1.y);
            }
        }
    }

    // ---- epilogue: normalize by l, write y[B*T, C] ----
    const int b = bh >> 4, h = bh & 15;
    #pragma unroll
    for (int i = 0; i < 4; i++) {
        int r = ty + 16 * i;
        float inv = 1.0f / row_l[r];
        float2 c0 = f2unpack(po[i][0]), c1 = f2unpack(po[i][1]);
        float2 c2 = f2unpack(po[i][2]), c3 = f2unpack(po[i][3]);
        float4 o0 = make_float4(c0.x * inv, c0.y * inv, c1.x * inv, c1.y * inv);
        float4 o1 = make_float4(c2.x * inv, c2.y * inv, c3.x * inv, c3.y * inv);
        size_t yo = ((size_t)(b * T_) + q0 + r) * C_ + h * D_;
        *(float4*)&Yg[yo + (tx << 2)] = o0;
        *(float4*)&Yg[yo + 64 + (tx << 2)] = o1;
    }
}

// ---------------- launch --------------------------------------------------
extern "C" void kernel_launch(void* const* d_in, const int* in_sizes, int n_in,
                              void* d_out, int out_size)
{
    const float* x      = (const float*)d_in[0];
    const float* w_qkv  = (const float*)d_in[1];
    const float* w_proj = (const float*)d_in[2];
    const float* qw     = (const float*)d_in[3];
    const float* kw     = (const float*)d_in[4];
    float* out = (float*)d_out;

    float *qkv, *q, *k, *v, *y, *ct, *st;
    cudaGetSymbolAddress((void**)&qkv, g_qkv);
    cudaGetSymbolAddress((void**)&q,   g_q);
    cudaGetSymbolAddress((void**)&k,   g_k);
    cudaGetSymbolAddress((void**)&v,   g_v);
    cudaGetSymbolAddress((void**)&y,   g_y);
    cudaGetSymbolAddress((void**)&ct,  g_cos);
    cudaGetSymbolAddress((void**)&st,  g_sin);

    cudaFuncSetAttribute(flash_kernel,
                         cudaFuncAttributeMaxDynamicSharedMemorySize, FL_SMEM_BYTES);

    // 1) RoPE tables
    rope_table_kernel<<<(T_ * D_ + 255) / 256, 256>>>(ct, st);

    // 2) QKV GEMM: [B*T, C] @ [C, 3C]
    sgemm128_kernel<<<dim3((3 * C_) / 128, (B_ * T_) / 128), 256>>>(
        x, w_qkv, qkv, B_ * T_, 3 * C_, C_);

    // 3) RMSNorm + RoPE + split into [B,H,T,D]
    qkv_post_kernel<<<dim3(H_, T_, B_), 128>>>(qkv, qw, kw, ct, st, q, k, v);

    // 4) causal flash attention -> y [B*T, C]
    flash_kernel<<<dim3(T_ / 64, B_ * H_), 256, FL_SMEM_BYTES>>>(q, k, v, y);

    // 5) output projection: [B*T, C] @ [C, C]
    sgemm128_kernel<<<dim3(C_ / 128, (B_ * T_) / 128), 256>>>(
        y, w_proj, out, B_ * T_, C_, C_);
}

// round 5
// speedup vs baseline: 1.6570x; 1.6570x over previous
#include <cuda_runtime.h>
#include <cuda_bf16.h>
#include <cstdint>
#include <cstddef>

#define B_ 2
#define T_ 2048
#define C_ 2048
#define H_ 16
#define D_ 128
#define EPS_ 1.1920929e-07f

typedef unsigned long long u64t;

// ---------------- f32x2 packed-FMA helpers (Blackwell FFMA2) ----------------
__device__ __forceinline__ u64t f2pack(float a, float b) {
    u64t r; asm("mov.b64 %0, {%1,%2};" : "=l"(r) : "f"(a), "f"(b)); return r;
}
__device__ __forceinline__ float2 f2unpack(u64t v) {
    float lo, hi; asm("mov.b64 {%0,%1}, %2;" : "=f"(lo), "=f"(hi) : "l"(v));
    return make_float2(lo, hi);
}
__device__ __forceinline__ void f2fma(u64t& d, u64t a, u64t b) {
    asm("fma.rn.f32x2 %0, %1, %2, %0;" : "+l"(d) : "l"(a), "l"(b));
}
__device__ __forceinline__ void f2mul(u64t& d, u64t a) {
    asm("mul.rn.f32x2 %0, %0, %1;" : "+l"(d) : "l"(a));
}

// ---------------- mma.sync / ldmatrix / cp.async helpers (sm_80+ portable) --
__device__ __forceinline__ uint32_t smem_u32_of(const void* p) {
    uint32_t a;
    asm("{ .reg .u64 t; cvta.to.shared.u64 t, %1; cvt.u32.u64 %0, t; }"
        : "=r"(a) : "l"(p));
    return a;
}
__device__ __forceinline__ void ldsm4(uint32_t* r, uint32_t addr) {
    asm volatile("ldmatrix.sync.aligned.m8n8.x4.shared.b16 {%0,%1,%2,%3}, [%4];"
        : "=r"(r[0]), "=r"(r[1]), "=r"(r[2]), "=r"(r[3]) : "r"(addr));
}
__device__ __forceinline__ void mma_bf16(float* c, const uint32_t* a,
                                         uint32_t b0, uint32_t b1) {
    asm volatile(
        "mma.sync.aligned.m16n8k16.row.col.f32.bf16.bf16.f32 "
        "{%0,%1,%2,%3}, {%4,%5,%6,%7}, {%8,%9}, {%0,%1,%2,%3};"
        : "+f"(c[0]), "+f"(c[1]), "+f"(c[2]), "+f"(c[3])
        : "r"(a[0]), "r"(a[1]), "r"(a[2]), "r"(a[3]), "r"(b0), "r"(b1));
}
__device__ __forceinline__ void cp16(uint32_t dst, const void* src) {
    asm volatile("cp.async.cg.shared.global [%0], [%1], 16;"
        :: "r"(dst), "l"(src));
}
#define CP_COMMIT() asm volatile("cp.async.commit_group;" ::: "memory")
#define CP_WAIT1()  asm volatile("cp.async.wait_group 1;" ::: "memory")
#define CP_WAIT0()  asm volatile("cp.async.wait_group 0;" ::: "memory")

// ---------------- scratch (static device globals; no runtime alloc) ---------
__device__ float g_qkv[(size_t)B_ * T_ * 3 * C_];        // [B*T, 3C]
__device__ float g_q[(size_t)B_ * H_ * T_ * D_];         // [B*H, T, D]
__device__ float g_k[(size_t)B_ * H_ * T_ * D_];
__device__ float g_v[(size_t)B_ * H_ * T_ * D_];
__device__ float g_y[(size_t)B_ * T_ * C_];              // [B*T, C]
__device__ float g_cos[(size_t)T_ * D_];
__device__ float g_sin[(size_t)T_ * D_];
// bf16 split operands: A2 [M, 2K] (hi | lo), Bt2 [N, 2K] (hi | lo), K = 2048
__device__ __nv_bfloat16 g_a2[(size_t)(B_ * T_) * (2 * C_)];        // 4096 x 4096
__device__ __nv_bfloat16 g_bt2[(size_t)(3 * C_) * (2 * C_)];        // 6144 x 4096

// ---------------- RoPE tables (double pow -> fp32, mirrors JAX rounding) ----
__global__ void rope_table_kernel(float* __restrict__ ct, float* __restrict__ st) {
    int idx = blockIdx.x * 256 + threadIdx.x;
    if (idx >= T_ * D_) return;
    int t = idx >> 7;
    int d = idx & 127;
    int j = d & 63;
    double inv = 1.0 / pow(1.0e6, (double)j / 64.0);
    float inv_f = (float)inv;
    float freq = (float)t * inv_f;
    ct[idx] = cosf(freq);
    st[idx] = sinf(freq);
}

// ---------------- bf16 hi/lo split: X[M,K] fp32 -> A2[M,2K] bf16 ------------
__global__ void split_rows_kernel(const float* __restrict__ X,
                                  __nv_bfloat16* __restrict__ A2,
                                  int Mrows, int K)
{
    int idx4 = blockIdx.x * 256 + threadIdx.x;
    size_t base = (size_t)idx4 * 4;
    if (base >= (size_t)Mrows * K) return;
    int r = (int)(base / K);
    int c = (int)(base % K);
    float4 v = *(const float4*)&X[base];
    __nv_bfloat16 h0 = __float2bfloat16_rn(v.x);
    __nv_bfloat16 h1 = __float2bfloat16_rn(v.y);
    __nv_bfloat16 h2 = __float2bfloat16_rn(v.z);
    __nv_bfloat16 h3 = __float2bfloat16_rn(v.w);
    __nv_bfloat16 l0 = __float2bfloat16_rn(v.x - __bfloat162float(h0));
    __nv_bfloat16 l1 = __float2bfloat16_rn(v.y - __bfloat162float(h1));
    __nv_bfloat16 l2 = __float2bfloat16_rn(v.z - __bfloat162float(h2));
    __nv_bfloat16 l3 = __float2bfloat16_rn(v.w - __bfloat162float(h3));
    size_t ob = (size_t)r * (2 * K) + c;
    __nv_bfloat162* ph = (__nv_bfloat162*)&A2[ob];
    __nv_bfloat162* pl = (__nv_bfloat162*)&A2[ob + K];
    ph[0] = __nv_bfloat162(h0, h1); ph[1] = __nv_bfloat162(h2, h3);
    pl[0] = __nv_bfloat162(l0, l1); pl[1] = __nv_bfloat162(l2, l3);
}

// ------- transpose + split: W[K,N] fp32 -> Bt2[N,2K] bf16 (K-major) ---------
__global__ void split_trans_kernel(const float* __restrict__ W,
                                   __nv_bfloat16* __restrict__ Bt2,
                                   int K, int N)
{
    __shared__ float tile[32][33];
    const int tx = threadIdx.x & 31, ty = threadIdx.x >> 5;
    const int n0 = blockIdx.x * 32, k0 = blockIdx.y * 32;
    #pragma unroll
    for (int i = 0; i < 4; ++i)
        tile[ty + i * 8][tx] = W[(size_t)(k0 + ty + i * 8) * N + n0 + tx];
    __syncthreads();
    const int K2 = 2 * K;
    #pragma unroll
    for (int i = 0; i < 4; ++i) {
        int n = n0 + ty + i * 8;
        int k = k0 + tx;
        float v = tile[tx][ty + i * 8];
        __nv_bfloat16 h = __float2bfloat16_rn(v);
        __nv_bfloat16 l = __float2bfloat16_rn(v - __bfloat162float(h));
        Bt2[(size_t)n * K2 + k] = h;
        Bt2[(size_t)n * K2 + K + k] = l;
    }
}

// ================= bf16x3 mma.sync GEMM =====================================
// C[M,N] = A[M,K] @ W[K,N] in fp32-equivalent precision via 3 bf16 products:
//   hi@hi + lo@hi + hi@lo, expressed as one GEMM over K' = 3K with
//   segment-mapped pointers into A2[M,2K], Bt2[N,2K].
// Block 128x128, 8 warps (warp tile 64x32), KT=64, 2-stage cp.async pipeline.
#define GBM 128
#define GBN 128
#define GBK 64
#define GSTRIDE 72                    // bf16 elems per smem row (144 B, padded)
#define GST_BYTES (128 * GSTRIDE * 2) // 18432 per operand per stage
#define GSA(s) ((s) * GST_BYTES)
#define GSB(s) (2 * GST_BYTES + (s) * GST_BYTES)
#define GEMM_SMEM_BYTES (4 * GST_BYTES)   // 73728

__global__ __launch_bounds__(256, 2) void gemm_bf16x3_kernel(
    const __nv_bfloat16* __restrict__ A2, const __nv_bfloat16* __restrict__ B2,
    float* __restrict__ Cm, int M, int N, int K)
{
    extern __shared__ char gsm[];
    const uint32_t sb = smem_u32_of(gsm);
    const int tid = threadIdx.x;
    const int lane = tid & 31, wid = tid >> 5;
    const int warp_m = wid >> 2;          // 0..1 -> rows warp_m*64
    const int warp_n = wid & 3;           // 0..3 -> cols warp_n*32
    const int m0 = blockIdx.y * GBM;
    const int n0 = blockIdx.x * GBN;
    const int K2 = 2 * K;
    const int niter = (3 * K) / GBK;

    float acc[4][4][4];
    #pragma unroll
    for (int i = 0; i < 4; i++)
        #pragma unroll
        for (int j = 0; j < 4; j++)
            #pragma unroll
            for (int q = 0; q < 4; q++) acc[i][j][q] = 0.0f;

    // stage loader: 1024 16B chunks per operand, 4 per thread per operand
    auto load_stage = [&](int kt, int s) {
        int kp = kt * GBK;
        int seg = kp >> 11;               // kp / 2048  (K == 2048 here)
        int koff = kp & (K - 1);
        const __nv_bfloat16* Ap = A2 + (size_t)m0 * K2 + ((seg == 1) ? K : 0) + koff;
        const __nv_bfloat16* Bp = B2 + (size_t)n0 * K2 + ((seg == 2) ? K : 0) + koff;
        #pragma unroll
        for (int u = 0; u < 4; ++u) {
            int idx = u * 256 + tid;      // 0..1023
            int r = idx >> 3;             // row 0..127
            int c = (idx & 7) * 8;        // elem col (16B chunk)
            cp16(sb + GSA(s) + r * (GSTRIDE * 2) + c * 2, Ap + (size_t)r * K2 + c);
            cp16(sb + GSB(s) + r * (GSTRIDE * 2) + c * 2, Bp + (size_t)r * K2 + c);
        }
    };

    load_stage(0, 0);
    CP_COMMIT();

    for (int kt = 0; kt < niter; ++kt) {
        const int s = kt & 1;
        if (kt + 1 < niter) {
            load_stage(kt + 1, (kt + 1) & 1);
            CP_COMMIT();
            CP_WAIT1();
        } else {
            CP_WAIT0();
        }
        __syncthreads();

        const uint32_t abase = sb + GSA(s);
        const uint32_t bbase = sb + GSB(s);
        const int arow = warp_m * 64 + (lane & 15);
        const int acol = (lane >> 4) << 3;
        const int brow = warp_n * 32 + ((lane >> 4) << 3) + (lane & 7);
        const int bcol = ((lane >> 3) & 1) << 3;

        #pragma unroll
        for (int ks = 0; ks < 4; ++ks) {
            const int kb = ks * 16;
            uint32_t af[4][4], bf[2][4];
            #pragma unroll
            for (int im = 0; im < 4; ++im)
                ldsm4(af[im], abase + (arow + im * 16) * (GSTRIDE * 2)
                                    + (kb + acol) * 2);
            #pragma unroll
            for (int j2 = 0; j2 < 2; ++j2)
                ldsm4(bf[j2], bbase + (brow + j2 * 16) * (GSTRIDE * 2)
                                    + (kb + bcol) * 2);
            #pragma unroll
            for (int im = 0; im < 4; ++im)
                #pragma unroll
                for (int jn = 0; jn < 4; ++jn)
                    mma_bf16(acc[im][jn], af[im],
                             bf[jn >> 1][(jn & 1) * 2],
                             bf[jn >> 1][(jn & 1) * 2 + 1]);
        }
        __syncthreads();   // protect stage s from overwrite at iter kt+2
    }

    // epilogue
    const int g = lane >> 2, t4 = lane & 3;
    #pragma unroll
    for (int im = 0; im < 4; ++im) {
        const int r0 = m0 + warp_m * 64 + im * 16 + g;
        #pragma unroll
        for (int jn = 0; jn < 4; ++jn) {
            const int col = n0 + warp_n * 32 + jn * 8 + 2 * t4;
            *(float2*)&Cm[(size_t)r0 * N + col] =
                make_float2(acc[im][jn][0], acc[im][jn][1]);
            *(float2*)&Cm[(size_t)(r0 + 8) * N + col] =
                make_float2(acc[im][jn][2], acc[im][jn][3]);
        }
    }
}

// ---------------- fused per-head RMSNorm + RoPE + QKV split -----------------
__global__ void qkv_post_kernel(
    const float* __restrict__ qkv,
    const float* __restrict__ qw, const float* __restrict__ kw,
    const float* __restrict__ ct, const float* __restrict__ st,
    float* __restrict__ Qo, float* __restrict__ Ko, float* __restrict__ Vo)
{
    const int h = blockIdx.x, t = blockIdx.y, b = blockIdx.z;
    const int d = threadIdx.x;
    const size_t base = ((size_t)(b * T_ + t)) * (3 * C_);

    float qv = qkv[base + h * D_ + d];
    float kv = qkv[base + C_ + h * D_ + d];
    float vv = qkv[base + 2 * C_ + h * D_ + d];

    __shared__ float sq[128], sk[128], red[8];

    float s2q = qv * qv, s2k = kv * kv;
    #pragma unroll
    for (int o = 16; o; o >>= 1) {
        s2q += __shfl_xor_sync(0xffffffffu, s2q, o);
        s2k += __shfl_xor_sync(0xffffffffu, s2k, o);
    }
    int w = d >> 5;
    if ((d & 31) == 0) { red[w] = s2q; red[4 + w] = s2k; }
    __syncthreads();
    float sumq = red[0] + red[1] + red[2] + red[3];
    float sumk = red[4] + red[5] + red[6] + red[7];
    float rq = rsqrtf(sumq * (1.0f / 128.0f) + EPS_) * qw[d];
    float rk = rsqrtf(sumk * (1.0f / 128.0f) + EPS_) * kw[d];
    sq[d] = qv * rq;
    sk[d] = kv * rk;
    __syncthreads();

    float c = ct[t * D_ + d], s = st[t * D_ + d];
    float qrot = (d < 64) ? -sq[d + 64] : sq[d - 64];
    float krot = (d < 64) ? -sk[d + 64] : sk[d - 64];
    float qo = sq[d] * c + qrot * s;
    float ko = sk[d] * c + krot * s;

    size_t oidx = (((size_t)(b * H_ + h)) * T_ + t) * D_ + d;
    Qo[oidx] = qo;
    Ko[oidx] = ko;
    Vo[oidx] = vv;
}

// ---------------- causal flash attention (fp32, f32x2 math) -----------------
#define FL_SMEM_FLOATS (8192 + 8448 + 8192 + 4160 + 192)
#define FL_SMEM_BYTES  (FL_SMEM_FLOATS * 4)

__global__ __launch_bounds__(256, 1) void flash_kernel(
    const float* __restrict__ Qg, const float* __restrict__ Kg,
    const float* __restrict__ Vg, float* __restrict__ Yg)
{
    extern __shared__ float sm[];
    float* Qs = sm;                         // [64][128]
    float* Ks = sm + 8192;                  // [64][132] (padded)
    float* Vs = sm + 8192 + 8448;           // [64][128]
    float* Ss = Vs + 8192;                  // [64][65]
    float* row_m = Ss + 4160;               // [64]
    float* row_l = row_m + 64;
    float* row_a = row_l + 64;

    const int tid = threadIdx.x;
    const int tx = tid & 15, ty = tid >> 4;
    const int bh = blockIdx.y;
    const int q0 = blockIdx.x << 6;

    const float* Qp = Qg + ((size_t)bh * T_ + q0) * D_;
    const float* Kp = Kg + (size_t)bh * T_ * D_;
    const float* Vp = Vg + (size_t)bh * T_ * D_;

    #pragma unroll
    for (int s = tid; s < 64 * 32; s += 256) {
        int r = s >> 5, c4 = (s & 31) << 2;
        *(float4*)&Qs[r * 128 + c4] = *(const float4*)&Qp[(size_t)r * D_ + c4];
    }
    if (tid < 64) { row_m[tid] = -3.0e38f; row_l[tid] = 0.0f; }

    u64t po[4][4];
    #pragma unroll
    for (int i = 0; i < 4; i++)
        #pragma unroll
        for (int j = 0; j < 4; j++) po[i][j] = 0ull;

    const int ktiles = (q0 >> 6) + 1;
    for (int kt = 0; kt < ktiles; ++kt) {
        const int k0 = kt << 6;
        __syncthreads();

        #pragma unroll
        for (int s = tid; s < 64 * 32; s += 256) {
            int r = s >> 5, c4 = (s & 31) << 2;
            *(float4*)&Ks[r * 132 + c4] = *(const float4*)&Kp[((size_t)(k0 + r)) * D_ + c4];
            *(float4*)&Vs[r * 128 + c4] = *(const float4*)&Vp[((size_t)(k0 + r)) * D_ + c4];
        }
        __syncthreads();

        u64t ps[4][4];
        #pragma unroll
        for (int i = 0; i < 4; i++)
            #pragma unroll
            for (int j = 0; j < 4; j++) ps[i][j] = 0ull;

        #pragma unroll 4
        for (int dc = 0; dc < 32; ++dc) {
            ulonglong2 qv[4], kv[4];
            #pragma unroll
            for (int i = 0; i < 4; i++)
                qv[i] = *(const ulonglong2*)&Qs[(ty + 16 * i) * 128 + (dc << 2)];
            #pragma unroll
            for (int j = 0; j < 4; j++)
                kv[j] = *(const ulonglong2*)&Ks[(tx + 16 * j) * 132 + (dc << 2)];
            #pragma unroll
            for (int i = 0; i < 4; i++)
                #pragma unroll
                for (int j = 0; j < 4; j++) {
                    f2fma(ps[i][j], qv[i].x, kv[j].x);
                    f2fma(ps[i][j], qv[i].y, kv[j].y);
                }
        }

        const bool diag = (k0 == q0);
        #pragma unroll
        for (int i = 0; i < 4; i++) {
            int ri = ty + 16 * i;
            #pragma unroll
            for (int j = 0; j < 4; j++) {
                int cj = tx + 16 * j;
                float2 f = f2unpack(ps[i][j]);
                float sv = (f.x + f.y) * (1.0f / 128.0f);
                if (diag && cj > ri) sv = -3.0e38f;
                Ss[ri * 65 + cj] = sv;
            }
        }
        __syncthreads();

        {
            int r = tid >> 2, c0 = (tid & 3) << 4;
            float mloc = -3.0e38f;
            #pragma unroll
            for (int jj = 0; jj < 16; jj++) mloc = fmaxf(mloc, Ss[r * 65 + c0 + jj]);
            mloc = fmaxf(mloc, __shfl_xor_sync(0xffffffffu, mloc, 1));
            mloc = fmaxf(mloc, __shfl_xor_sync(0xffffffffu, mloc, 2));
            if ((tid & 3) == 0) {
                float m_old = row_m[r];
                float m = fmaxf(m_old, mloc);
                float a = __expf(m_old - m);
                row_a[r] = a; row_m[r] = m; row_l[r] *= a;
            }
        }
        __syncthreads();
        {
            int r = tid >> 2, c0 = (tid & 3) << 4;
            float m = row_m[r], sum = 0.0f;
            #pragma unroll
            for (int jj = 0; jj < 16; jj++) {
                float p = __expf(Ss[r * 65 + c0 + jj] - m);
                Ss[r * 65 + c0 + jj] = p;
                sum += p;
            }
            sum += __shfl_xor_sync(0xffffffffu, sum, 1);
            sum += __shfl_xor_sync(0xffffffffu, sum, 2);
            if ((tid & 3) == 0) row_l[r] += sum;
        }
        __syncthreads();

        #pragma unroll
        for (int i = 0; i < 4; i++) {
            float a = row_a[ty + 16 * i];
            u64t pa = f2pack(a, a);
            #pragma unroll
            for (int jp = 0; jp < 4; jp++) f2mul(po[i][jp], pa);
        }

        #pragma unroll 4
        for (int kk = 0; kk < 64; ++kk) {
            ulonglong2 v0 = *(const ulonglong2*)&Vs[kk * 128 + (tx << 2)];
            ulonglong2 v1 = *(const ulonglong2*)&Vs[kk * 128 + 64 + (tx << 2)];
            #pragma unroll
            for (int i = 0; i < 4; i++) {
                float p = Ss[(ty + 16 * i) * 65 + kk];
                u64t pp = f2pack(p, p);
                f2fma(po[i][0], pp, v0.x);
                f2fma(po[i][1], pp, v0.y);
                f2fma(po[i][2], pp, v1.x);
                f2fma(po[i][3], pp, v1.y);
            }
        }
    }

    const int b = bh >> 4, h = bh & 15;
    #pragma unroll
    for (int i = 0; i < 4; i++) {
        int r = ty + 16 * i;
        float inv = 1.0f / row_l[r];
        float2 c0 = f2unpack(po[i][0]), c1 = f2unpack(po[i][1]);
        float2 c2 = f2unpack(po[i][2]), c3 = f2unpack(po[i][3]);
        float4 o0 = make_float4(c0.x * inv, c0.y * inv, c1.x * inv, c1.y * inv);
        float4 o1 = make_float4(c2.x * inv, c2.y * inv, c3.x * inv, c3.y * inv);
        size_t yo = ((size_t)(b * T_) + q0 + r) * C_ + h * D_;
        *(float4*)&Yg[yo + (tx << 2)] = o0;
        *(float4*)&Yg[yo + 64 + (tx << 2)] = o1;
    }
}

// ---------------- launch --------------------------------------------------
extern "C" void kernel_launch(void* const* d_in, const int* in_sizes, int n_in,
                              void* d_out, int out_size)
{
    const float* x      = (const float*)d_in[0];
    const float* w_qkv  = (const float*)d_in[1];
    const float* w_proj = (const float*)d_in[2];
    const float* qw     = (const float*)d_in[3];
    const float* kw     = (const float*)d_in[4];
    float* out = (float*)d_out;

    float *qkv, *q, *k, *v, *y, *ct, *st;
    __nv_bfloat16 *a2, *bt2;
    cudaGetSymbolAddress((void**)&qkv, g_qkv);
    cudaGetSymbolAddress((void**)&q,   g_q);
    cudaGetSymbolAddress((void**)&k,   g_k);
    cudaGetSymbolAddress((void**)&v,   g_v);
    cudaGetSymbolAddress((void**)&y,   g_y);
    cudaGetSymbolAddress((void**)&ct,  g_cos);
    cudaGetSymbolAddress((void**)&st,  g_sin);
    cudaGetSymbolAddress((void**)&a2,  g_a2);
    cudaGetSymbolAddress((void**)&bt2, g_bt2);

    cudaFuncSetAttribute(flash_kernel,
                         cudaFuncAttributeMaxDynamicSharedMemorySize, FL_SMEM_BYTES);
    cudaFuncSetAttribute(gemm_bf16x3_kernel,
                         cudaFuncAttributeMaxDynamicSharedMemorySize, GEMM_SMEM_BYTES);

    const int M = B_ * T_;          // 4096
    const int K = C_;               // 2048
    const int N1 = 3 * C_;          // 6144

    // 1) RoPE tables
    rope_table_kernel<<<(T_ * D_ + 255) / 256, 256>>>(ct, st);

    // 2) split x -> a2, split w_qkv^T -> bt2
    split_rows_kernel<<<(int)(((size_t)M * K / 4 + 255) / 256), 256>>>(x, a2, M, K);
    split_trans_kernel<<<dim3(N1 / 32, K / 32), 256>>>(w_qkv, bt2, K, N1);

    // 3) QKV GEMM (bf16x3 tensor cores): [M,K] @ [K,N1]
    gemm_bf16x3_kernel<<<dim3(N1 / GBN, M / GBM), 256, GEMM_SMEM_BYTES>>>(
        a2, bt2, qkv, M, N1, K);

    // 4) RMSNorm + RoPE + split into [B,H,T,D]
    qkv_post_kernel<<<dim3(H_, T_, B_), 128>>>(qkv, qw, kw, ct, st, q, k, v);

    // 5) causal flash attention -> y [B*T, C]
    flash_kernel<<<dim3(T_ / 64, B_ * H_), 256, FL_SMEM_BYTES>>>(q, k, v, y);

    // 6) split y -> a2, split w_proj^T -> bt2
    split_rows_kernel<<<(int)(((size_t)M * K / 4 + 255) / 256), 256>>>(y, a2, M, K);
    split_trans_kernel<<<dim3(C_ / 32, K / 32), 256>>>(w_proj, bt2, K, C_);

    // 7) output projection (bf16x3): [M,K] @ [K,C]
    gemm_bf16x3_kernel<<<dim3(C_ / GBN, M / GBM), 256, GEMM_SMEM_BYTES>>>(
        a2, bt2, out, M, C_, K);
}

// round 7
// speedup vs baseline: 2.0868x; 1.2594x over previous
#include <cuda_runtime.h>
#include <cuda_bf16.h>
#include <cstdint>
#include <cstddef>

#define B_ 2
#define T_ 2048
#define C_ 2048
#define H_ 16
#define D_ 128
#define EPS_ 1.1920929e-07f

typedef unsigned long long u64t;

// ---------------- mma.sync / ldmatrix / cp.async helpers (sm_80+ portable) --
__device__ __forceinline__ uint32_t smem_u32_of(const void* p) {
    uint32_t a;
    asm("{ .reg .u64 t; cvta.to.shared.u64 t, %1; cvt.u32.u64 %0, t; }"
        : "=r"(a) : "l"(p));
    return a;
}
__device__ __forceinline__ void ldsm4(uint32_t* r, uint32_t addr) {
    asm volatile("ldmatrix.sync.aligned.m8n8.x4.shared.b16 {%0,%1,%2,%3}, [%4];"
        : "=r"(r[0]), "=r"(r[1]), "=r"(r[2]), "=r"(r[3]) : "r"(addr));
}
__device__ __forceinline__ void ldsm4t(uint32_t* r, uint32_t addr) {
    asm volatile("ldmatrix.sync.aligned.m8n8.x4.trans.shared.b16 {%0,%1,%2,%3}, [%4];"
        : "=r"(r[0]), "=r"(r[1]), "=r"(r[2]), "=r"(r[3]) : "r"(addr));
}
__device__ __forceinline__ void mma_bf16(float* c, const uint32_t* a,
                                         uint32_t b0, uint32_t b1) {
    asm volatile(
        "mma.sync.aligned.m16n8k16.row.col.f32.bf16.bf16.f32 "
        "{%0,%1,%2,%3}, {%4,%5,%6,%7}, {%8,%9}, {%0,%1,%2,%3};"
        : "+f"(c[0]), "+f"(c[1]), "+f"(c[2]), "+f"(c[3])
        : "r"(a[0]), "r"(a[1]), "r"(a[2]), "r"(a[3]), "r"(b0), "r"(b1));
}
__device__ __forceinline__ void cp16(uint32_t dst, const void* src) {
    asm volatile("cp.async.cg.shared.global [%0], [%1], 16;"
        :: "r"(dst), "l"(src));
}
#define CP_COMMIT() asm volatile("cp.async.commit_group;" ::: "memory")
#define CP_WAIT1()  asm volatile("cp.async.wait_group 1;" ::: "memory")
#define CP_WAIT0()  asm volatile("cp.async.wait_group 0;" ::: "memory")

// ---------------- scratch (static device globals; no runtime alloc) ---------
__device__ float g_qkv[(size_t)B_ * T_ * 3 * C_];        // [B*T, 3C]
__device__ float g_q[(size_t)B_ * H_ * T_ * D_];         // [B*H, T, D]
__device__ float g_k[(size_t)B_ * H_ * T_ * D_];
__device__ float g_v[(size_t)B_ * H_ * T_ * D_];
__device__ float g_y[(size_t)B_ * T_ * C_];              // [B*T, C]
__device__ float g_cos[(size_t)T_ * D_];
__device__ float g_sin[(size_t)T_ * D_];
// bf16 split operands: A2 [M, 2K] (hi | lo), Bt2 [N, 2K] (hi | lo), K = 2048
__device__ __nv_bfloat16 g_a2[(size_t)(B_ * T_) * (2 * C_)];        // 4096 x 4096
__device__ __nv_bfloat16 g_bt2[(size_t)(3 * C_) * (2 * C_)];        // 6144 x 4096

// ---------------- RoPE tables (double pow -> fp32, mirrors JAX rounding) ----
__global__ void rope_table_kernel(float* __restrict__ ct, float* __restrict__ st) {
    int idx = blockIdx.x * 256 + threadIdx.x;
    if (idx >= T_ * D_) return;
    int t = idx >> 7;
    int d = idx & 127;
    int j = d & 63;
    double inv = 1.0 / pow(1.0e6, (double)j / 64.0);
    float inv_f = (float)inv;
    float freq = (float)t * inv_f;
    ct[idx] = cosf(freq);
    st[idx] = sinf(freq);
}

// ---------------- bf16 hi/lo split: X[M,K] fp32 -> A2[M,2K] bf16 ------------
__global__ void split_rows_kernel(const float* __restrict__ X,
                                  __nv_bfloat16* __restrict__ A2,
                                  int Mrows, int K)
{
    int idx4 = blockIdx.x * 256 + threadIdx.x;
    size_t base = (size_t)idx4 * 4;
    if (base >= (size_t)Mrows * K) return;
    int r = (int)(base / K);
    int c = (int)(base % K);
    float4 v = *(const float4*)&X[base];
    __nv_bfloat16 h0 = __float2bfloat16_rn(v.x);
    __nv_bfloat16 h1 = __float2bfloat16_rn(v.y);
    __nv_bfloat16 h2 = __float2bfloat16_rn(v.z);
    __nv_bfloat16 h3 = __float2bfloat16_rn(v.w);
    __nv_bfloat16 l0 = __float2bfloat16_rn(v.x - __bfloat162float(h0));
    __nv_bfloat16 l1 = __float2bfloat16_rn(v.y - __bfloat162float(h1));
    __nv_bfloat16 l2 = __float2bfloat16_rn(v.z - __bfloat162float(h2));
    __nv_bfloat16 l3 = __float2bfloat16_rn(v.w - __bfloat162float(h3));
    size_t ob = (size_t)r * (2 * K) + c;
    __nv_bfloat162* ph = (__nv_bfloat162*)&A2[ob];
    __nv_bfloat162* pl = (__nv_bfloat162*)&A2[ob + K];
    ph[0] = __nv_bfloat162(h0, h1); ph[1] = __nv_bfloat162(h2, h3);
    pl[0] = __nv_bfloat162(l0, l1); pl[1] = __nv_bfloat162(l2, l3);
}

// ------- transpose + split: W[K,N] fp32 -> Bt2[N,2K] bf16 (K-major) ---------
__global__ void split_trans_kernel(const float* __restrict__ W,
                                   __nv_bfloat16* __restrict__ Bt2,
                                   int K, int N)
{
    __shared__ float tile[32][33];
    const int tx = threadIdx.x & 31, ty = threadIdx.x >> 5;
    const int n0 = blockIdx.x * 32, k0 = blockIdx.y * 32;
    #pragma unroll
    for (int i = 0; i < 4; ++i)
        tile[ty + i * 8][tx] = W[(size_t)(k0 + ty + i * 8) * N + n0 + tx];
    __syncthreads();
    const int K2 = 2 * K;
    #pragma unroll
    for (int i = 0; i < 4; ++i) {
        int n = n0 + ty + i * 8;
        int k = k0 + tx;
        float v = tile[tx][ty + i * 8];
        __nv_bfloat16 h = __float2bfloat16_rn(v);
        __nv_bfloat16 l = __float2bfloat16_rn(v - __bfloat162float(h));
        Bt2[(size_t)n * K2 + k] = h;
        Bt2[(size_t)n * K2 + K + k] = l;
    }
}

// ================= bf16x3 mma.sync GEMM =====================================
#define GBM 128
#define GBN 128
#define GBK 64
#define GSTRIDE 72
#define GST_BYTES (128 * GSTRIDE * 2)
#define GSA(s) ((s) * GST_BYTES)
#define GSB(s) (2 * GST_BYTES + (s) * GST_BYTES)
#define GEMM_SMEM_BYTES (4 * GST_BYTES)

__global__ __launch_bounds__(256, 2) void gemm_bf16x3_kernel(
    const __nv_bfloat16* __restrict__ A2, const __nv_bfloat16* __restrict__ B2,
    float* __restrict__ Cm, int M, int N, int K)
{
    extern __shared__ char gsm[];
    const uint32_t sb = smem_u32_of(gsm);
    const int tid = threadIdx.x;
    const int lane = tid & 31, wid = tid >> 5;
    const int warp_m = wid >> 2;
    const int warp_n = wid & 3;
    const int m0 = blockIdx.y * GBM;
    const int n0 = blockIdx.x * GBN;
    const int K2 = 2 * K;
    const int niter = (3 * K) / GBK;

    float acc[4][4][4];
    #pragma unroll
    for (int i = 0; i < 4; i++)
        #pragma unroll
        for (int j = 0; j < 4; j++)
            #pragma unroll
            for (int q = 0; q < 4; q++) acc[i][j][q] = 0.0f;

    auto load_stage = [&](int kt, int s) {
        int kp = kt * GBK;
        int seg = kp >> 11;
        int koff = kp & (K - 1);
        const __nv_bfloat16* Ap = A2 + (size_t)m0 * K2 + ((seg == 1) ? K : 0) + koff;
        const __nv_bfloat16* Bp = B2 + (size_t)n0 * K2 + ((seg == 2) ? K : 0) + koff;
        #pragma unroll
        for (int u = 0; u < 4; ++u) {
            int idx = u * 256 + tid;
            int r = idx >> 3;
            int c = (idx & 7) * 8;
            cp16(sb + GSA(s) + r * (GSTRIDE * 2) + c * 2, Ap + (size_t)r * K2 + c);
            cp16(sb + GSB(s) + r * (GSTRIDE * 2) + c * 2, Bp + (size_t)r * K2 + c);
        }
    };

    load_stage(0, 0);
    CP_COMMIT();

    for (int kt = 0; kt < niter; ++kt) {
        const int s = kt & 1;
        if (kt + 1 < niter) {
            load_stage(kt + 1, (kt + 1) & 1);
            CP_COMMIT();
            CP_WAIT1();
        } else {
            CP_WAIT0();
        }
        __syncthreads();

        const uint32_t abase = sb + GSA(s);
        const uint32_t bbase = sb + GSB(s);
        const int arow = warp_m * 64 + (lane & 15);
        const int acol = (lane >> 4) << 3;
        const int brow = warp_n * 32 + ((lane >> 4) << 3) + (lane & 7);
        const int bcol = ((lane >> 3) & 1) << 3;

        #pragma unroll
        for (int ks = 0; ks < 4; ++ks) {
            const int kb = ks * 16;
            uint32_t af[4][4], bf[2][4];
            #pragma unroll
            for (int im = 0; im < 4; ++im)
                ldsm4(af[im], abase + (arow + im * 16) * (GSTRIDE * 2)
                                    + (kb + acol) * 2);
            #pragma unroll
            for (int j2 = 0; j2 < 2; ++j2)
                ldsm4(bf[j2], bbase + (brow + j2 * 16) * (GSTRIDE * 2)
                                    + (kb + bcol) * 2);
            #pragma unroll
            for (int im = 0; im < 4; ++im)
                #pragma unroll
                for (int jn = 0; jn < 4; ++jn)
                    mma_bf16(acc[im][jn], af[im],
                             bf[jn >> 1][(jn & 1) * 2],
                             bf[jn >> 1][(jn & 1) * 2 + 1]);
        }
        __syncthreads();
    }

    const int g = lane >> 2, t4 = lane & 3;
    #pragma unroll
    for (int im = 0; im < 4; ++im) {
        const int r0 = m0 + warp_m * 64 + im * 16 + g;
        #pragma unroll
        for (int jn = 0; jn < 4; ++jn) {
            const int col = n0 + warp_n * 32 + jn * 8 + 2 * t4;
            *(float2*)&Cm[(size_t)r0 * N + col] =
                make_float2(acc[im][jn][0], acc[im][jn][1]);
            *(float2*)&Cm[(size_t)(r0 + 8) * N + col] =
                make_float2(acc[im][jn][2], acc[im][jn][3]);
        }
    }
}

// ---------------- fused per-head RMSNorm + RoPE + QKV split -----------------
__global__ void qkv_post_kernel(
    const float* __restrict__ qkv,
    const float* __restrict__ qw, const float* __restrict__ kw,
    const float* __restrict__ ct, const float* __restrict__ st,
    float* __restrict__ Qo, float* __restrict__ Ko, float* __restrict__ Vo)
{
    const int h = blockIdx.x, t = blockIdx.y, b = blockIdx.z;
    const int d = threadIdx.x;
    const size_t base = ((size_t)(b * T_ + t)) * (3 * C_);

    float qv = qkv[base + h * D_ + d];
    float kv = qkv[base + C_ + h * D_ + d];
    float vv = qkv[base + 2 * C_ + h * D_ + d];

    __shared__ float sq[128], sk[128], red[8];

    float s2q = qv * qv, s2k = kv * kv;
    #pragma unroll
    for (int o = 16; o; o >>= 1) {
        s2q += __shfl_xor_sync(0xffffffffu, s2q, o);
        s2k += __shfl_xor_sync(0xffffffffu, s2k, o);
    }
    int w = d >> 5;
    if ((d & 31) == 0) { red[w] = s2q; red[4 + w] = s2k; }
    __syncthreads();
    float sumq = red[0] + red[1] + red[2] + red[3];
    float sumk = red[4] + red[5] + red[6] + red[7];
    float rq = rsqrtf(sumq * (1.0f / 128.0f) + EPS_) * qw[d];
    float rk = rsqrtf(sumk * (1.0f / 128.0f) + EPS_) * kw[d];
    sq[d] = qv * rq;
    sk[d] = kv * rk;
    __syncthreads();

    float c = ct[t * D_ + d], s = st[t * D_ + d];
    float qrot = (d < 64) ? -sq[d + 64] : sq[d - 64];
    float krot = (d < 64) ? -sk[d + 64] : sk[d - 64];
    float qo = sq[d] * c + qrot * s;
    float ko = sk[d] * c + krot * s;

    size_t oidx = (((size_t)(b * H_ + h)) * T_ + t) * D_ + d;
    Qo[oidx] = qo;
    Ko[oidx] = ko;
    Vo[oidx] = vv;
}

// ============ causal flash attention (bf16x3 mma.sync tensor cores) =========
// BQ = BK = 64, D = 128, 256 threads (8 warps: 4 m-groups x 2 n-groups).
// Q/K/V smem: [64][264] bf16, cols 0-127 = hi, 128-255 = lo (pad 8).
// P smem: [64][136] bf16, cols 0-63 = hi, 64-127 = lo.
// S smem: [64][68] fp32.
#define FQP 264
#define FPP 136
#define FSP 68
#define FOFF_Q 0
#define FOFF_K 33792
#define FOFF_V 67584
#define FOFF_P 101376
#define FOFF_S 118784
#define FOFF_M 136192
#define FOFF_L 136448
#define FOFF_A 136704
#define FL2_SMEM_BYTES 136960

__device__ __forceinline__ void bsplit4(__nv_bfloat16* row, int c, int lo_off,
                                        float4 v) {
    __nv_bfloat16 h0 = __float2bfloat16_rn(v.x);
    __nv_bfloat16 h1 = __float2bfloat16_rn(v.y);
    __nv_bfloat16 h2 = __float2bfloat16_rn(v.z);
    __nv_bfloat16 h3 = __float2bfloat16_rn(v.w);
    __nv_bfloat16 l0 = __float2bfloat16_rn(v.x - __bfloat162float(h0));
    __nv_bfloat16 l1 = __float2bfloat16_rn(v.y - __bfloat162float(h1));
    __nv_bfloat16 l2 = __float2bfloat16_rn(v.z - __bfloat162float(h2));
    __nv_bfloat16 l3 = __float2bfloat16_rn(v.w - __bfloat162float(h3));
    *(__nv_bfloat162*)&row[c]     = __nv_bfloat162(h0, h1);
    *(__nv_bfloat162*)&row[c + 2] = __nv_bfloat162(h2, h3);
    *(__nv_bfloat162*)&row[c + lo_off]     = __nv_bfloat162(l0, l1);
    *(__nv_bfloat162*)&row[c + lo_off + 2] = __nv_bfloat162(l2, l3);
}

__global__ __launch_bounds__(256, 1) void flash_mma_kernel(
    const float* __restrict__ Qg, const float* __restrict__ Kg,
    const float* __restrict__ Vg, float* __restrict__ Yg)
{
    extern __shared__ char fsm[];
    const uint32_t sb = smem_u32_of(fsm);
    __nv_bfloat16* Q2 = (__nv_bfloat16*)(fsm + FOFF_Q);
    __nv_bfloat16* K2 = (__nv_bfloat16*)(fsm + FOFF_K);
    __nv_bfloat16* V2 = (__nv_bfloat16*)(fsm + FOFF_V);
    __nv_bfloat16* P2 = (__nv_bfloat16*)(fsm + FOFF_P);
    float* Ss    = (float*)(fsm + FOFF_S);
    float* row_m = (float*)(fsm + FOFF_M);
    float* row_l = (float*)(fsm + FOFF_L);
    float* row_a = (float*)(fsm + FOFF_A);

    const int tid = threadIdx.x;
    const int lane = tid & 31, wid = tid >> 5;
    const int wm = wid >> 1;            // 0..3 -> q rows wm*16
    const int wn = wid & 1;             // 0..1
    const int g = lane >> 2, t4 = lane & 3;
    const int bh = blockIdx.y;
    const int q0 = blockIdx.x << 6;

    const float* Qp = Qg + ((size_t)bh * T_ + q0) * D_;
    const float* Kp = Kg + (size_t)bh * T_ * D_;
    const float* Vp = Vg + (size_t)bh * T_ * D_;

    // load + split Q tile once
    #pragma unroll
    for (int u = 0; u < 8; ++u) {
        int idx = u * 256 + tid;
        int r = idx >> 5, c = (idx & 31) << 2;
        bsplit4(&Q2[r * FQP], c, 128, *(const float4*)&Qp[(size_t)r * D_ + c]);
    }
    if (tid < 64) { row_m[tid] = -3.0e38f; row_l[tid] = 0.0f; }

    float po[8][4];
    #pragma unroll
    for (int i = 0; i < 8; i++)
        #pragma unroll
        for (int j = 0; j < 4; j++) po[i][j] = 0.0f;

    const int ktiles = (q0 >> 6) + 1;
    for (int kt = 0; kt < ktiles; ++kt) {
        const int k0 = kt << 6;
        __syncthreads();   // previous tile fully consumed; Q/stat init done

        // load + split K, V tiles
        #pragma unroll
        for (int u = 0; u < 8; ++u) {
            int idx = u * 256 + tid;
            int r = idx >> 5, c = (idx & 31) << 2;
            bsplit4(&K2[r * FQP], c, 128,
                    *(const float4*)&Kp[((size_t)(k0 + r)) * D_ + c]);
            bsplit4(&V2[r * FQP], c, 128,
                    *(const float4*)&Vp[((size_t)(k0 + r)) * D_ + c]);
        }
        __syncthreads();

        // ---- S = Q K^T (3-term bf16, warp tile m16 n32) ----
        float ps[4][4];
        #pragma unroll
        for (int i = 0; i < 4; i++)
            #pragma unroll
            for (int j = 0; j < 4; j++) ps[i][j] = 0.0f;

        #pragma unroll
        for (int seg = 0; seg < 3; ++seg) {
            const int ao = (seg == 1) ? 128 : 0;
            const int bo = (seg == 2) ? 128 : 0;
            #pragma unroll
            for (int kb = 0; kb < 8; ++kb) {
                const int kc = kb * 16;
                uint32_t af[4];
                ldsm4(af, sb + FOFF_Q +
                      ((wm * 16 + (lane & 15)) * FQP + ao + kc + ((lane >> 4) << 3)) * 2);
                uint32_t bfr[2][4];
                #pragma unroll
                for (int j2 = 0; j2 < 2; ++j2) {
                    int brow = wn * 32 + j2 * 16 + ((lane >> 4) << 3) + (lane & 7);
                    ldsm4(bfr[j2], sb + FOFF_K +
                          (brow * FQP + bo + kc + (((lane >> 3) & 1) << 3)) * 2);
                }
                #pragma unroll
                for (int jn = 0; jn < 4; ++jn)
                    mma_bf16(ps[jn], af, bfr[jn >> 1][(jn & 1) * 2],
                             bfr[jn >> 1][(jn & 1) * 2 + 1]);
            }
        }

        // scale + causal mask + store S (fp32)
        const bool diag = (k0 == q0);
        #pragma unroll
        for (int jn = 0; jn < 4; ++jn) {
            int col = wn * 32 + jn * 8 + t4 * 2;
            int r0 = wm * 16 + g;
            float s0 = ps[jn][0] * (1.0f / 128.0f);
            float s1 = ps[jn][1] * (1.0f / 128.0f);
            float s2 = ps[jn][2] * (1.0f / 128.0f);
            float s3 = ps[jn][3] * (1.0f / 128.0f);
            if (diag) {
                if (col     > r0)     s0 = -3.0e38f;
                if (col + 1 > r0)     s1 = -3.0e38f;
                if (col     > r0 + 8) s2 = -3.0e38f;
                if (col + 1 > r0 + 8) s3 = -3.0e38f;
            }
            *(float2*)&Ss[r0 * FSP + col]       = make_float2(s0, s1);
            *(float2*)&Ss[(r0 + 8) * FSP + col] = make_float2(s2, s3);
        }
        __syncthreads();

        // ---- online softmax pass 1: row max update ----
        {
            int r = tid >> 2, c0 = (tid & 3) << 4;
            float mloc = -3.0e38f;
            #pragma unroll
            for (int jj = 0; jj < 16; jj++)
                mloc = fmaxf(mloc, Ss[r * FSP + c0 + jj]);
            mloc = fmaxf(mloc, __shfl_xor_sync(0xffffffffu, mloc, 1));
            mloc = fmaxf(mloc, __shfl_xor_sync(0xffffffffu, mloc, 2));
            if ((tid & 3) == 0) {
                float m_old = row_m[r];
                float m = fmaxf(m_old, mloc);
                float a = __expf(m_old - m);
                row_a[r] = a; row_m[r] = m; row_l[r] *= a;
            }
        }
        __syncthreads();

        // ---- pass 2: exp, write P hi/lo (bf16), row sum ----
        {
            int r = tid >> 2, c0 = (tid & 3) << 4;
            float m = row_m[r], sum = 0.0f;
            #pragma unroll
            for (int jj = 0; jj < 16; jj++) {
                float p = __expf(Ss[r * FSP + c0 + jj] - m);
                sum += p;
                __nv_bfloat16 h = __float2bfloat16_rn(p);
                __nv_bfloat16 l = __float2bfloat16_rn(p - __bfloat162float(h));
                P2[r * FPP + c0 + jj] = h;
                P2[r * FPP + 64 + c0 + jj] = l;
            }
            sum += __shfl_xor_sync(0xffffffffu, sum, 1);
            sum += __shfl_xor_sync(0xffffffffu, sum, 2);
            if ((tid & 3) == 0) row_l[r] += sum;
        }
        __syncthreads();

        // ---- rescale O accumulators ----
        {
            float a0 = row_a[wm * 16 + g];
            float a8 = row_a[wm * 16 + g + 8];
            #pragma unroll
            for (int jb = 0; jb < 8; ++jb) {
                po[jb][0] *= a0; po[jb][1] *= a0;
                po[jb][2] *= a8; po[jb][3] *= a8;
            }
        }

        // ---- O += P V (3-term bf16, warp tile m16 n64, V via ldmatrix.trans)
        #pragma unroll
        for (int seg = 0; seg < 3; ++seg) {
            const int ao = (seg == 1) ? 64 : 0;
            const int vo = (seg == 2) ? 128 : 0;
            #pragma unroll
            for (int kb = 0; kb < 4; ++kb) {
                const int kc = kb * 16;
                uint32_t af[4];
                ldsm4(af, sb + FOFF_P +
                      ((wm * 16 + (lane & 15)) * FPP + ao + kc + ((lane >> 4) << 3)) * 2);
                #pragma unroll
                for (int nb = 0; nb < 4; ++nb) {
                    uint32_t bfr[4];
                    int vrow = kc + (((lane >> 3) & 1) << 3) + (lane & 7);
                    int vcol = vo + wn * 64 + nb * 16 + ((lane >> 4) << 3);
                    ldsm4t(bfr, sb + FOFF_V + (vrow * FQP + vcol) * 2);
                    mma_bf16(po[nb * 2],     af, bfr[0], bfr[1]);
                    mma_bf16(po[nb * 2 + 1], af, bfr[2], bfr[3]);
                }
            }
        }
    }

    // ---- epilogue: normalize by l, write y[B*T, C] ----
    const int b = bh >> 4, h = bh & 15;
    const float inv0 = 1.0f / row_l[wm * 16 + g];
    const float inv8 = 1.0f / row_l[wm * 16 + g + 8];
    #pragma unroll
    for (int jb = 0; jb < 8; ++jb) {
        int dcol = wn * 64 + (jb >> 1) * 16 + (jb & 1) * 8 + t4 * 2;
        size_t row0 = (size_t)(b * T_) + q0 + wm * 16 + g;
        *(float2*)&Yg[row0 * C_ + h * D_ + dcol] =
            make_float2(po[jb][0] * inv0, po[jb][1] * inv0);
        *(float2*)&Yg[(row0 + 8) * C_ + h * D_ + dcol] =
            make_float2(po[jb][2] * inv8, po[jb][3] * inv8);
    }
}

// ---------------- launch --------------------------------------------------
extern "C" void kernel_launch(void* const* d_in, const int* in_sizes, int n_in,
                              void* d_out, int out_size)
{
    const float* x      = (const float*)d_in[0];
    const float* w_qkv  = (const float*)d_in[1];
    const float* w_proj = (const float*)d_in[2];
    const float* qw     = (const float*)d_in[3];
    const float* kw     = (const float*)d_in[4];
    float* out = (float*)d_out;

    float *qkv, *q, *k, *v, *y, *ct, *st;
    __nv_bfloat16 *a2, *bt2;
    cudaGetSymbolAddress((void**)&qkv, g_qkv);
    cudaGetSymbolAddress((void**)&q,   g_q);
    cudaGetSymbolAddress((void**)&k,   g_k);
    cudaGetSymbolAddress((void**)&v,   g_v);
    cudaGetSymbolAddress((void**)&y,   g_y);
    cudaGetSymbolAddress((void**)&ct,  g_cos);
    cudaGetSymbolAddress((void**)&st,  g_sin);
    cudaGetSymbolAddress((void**)&a2,  g_a2);
    cudaGetSymbolAddress((void**)&bt2, g_bt2);

    cudaFuncSetAttribute(flash_mma_kernel,
                         cudaFuncAttributeMaxDynamicSharedMemorySize, FL2_SMEM_BYTES);
    cudaFuncSetAttribute(gemm_bf16x3_kernel,
                         cudaFuncAttributeMaxDynamicSharedMemorySize, GEMM_SMEM_BYTES);

    const int M = B_ * T_;          // 4096
    const int K = C_;               // 2048
    const int N1 = 3 * C_;          // 6144

    // 1) RoPE tables
    rope_table_kernel<<<(T_ * D_ + 255) / 256, 256>>>(ct, st);

    // 2) split x -> a2, split w_qkv^T -> bt2
    split_rows_kernel<<<(int)(((size_t)M * K / 4 + 255) / 256), 256>>>(x, a2, M, K);
    split_trans_kernel<<<dim3(N1 / 32, K / 32), 256>>>(w_qkv, bt2, K, N1);

    // 3) QKV GEMM (bf16x3 tensor cores): [M,K] @ [K,N1]
    gemm_bf16x3_kernel<<<dim3(N1 / GBN, M / GBM), 256, GEMM_SMEM_BYTES>>>(
        a2, bt2, qkv, M, N1, K);

    // 4) RMSNorm + RoPE + split into [B,H,T,D]
    qkv_post_kernel<<<dim3(H_, T_, B_), 128>>>(qkv, qw, kw, ct, st, q, k, v);

    // 5) causal flash attention (tensor cores) -> y [B*T, C]
    flash_mma_kernel<<<dim3(T_ / 64, B_ * H_), 256, FL2_SMEM_BYTES>>>(q, k, v, y);

    // 6) split y -> a2, split w_proj^T -> bt2
    split_rows_kernel<<<(int)(((size_t)M * K / 4 + 255) / 256), 256>>>(y, a2, M, K);
    split_trans_kernel<<<dim3(C_ / 32, K / 32), 256>>>(w_proj, bt2, K, C_);

    // 7) output projection (bf16x3): [M,K] @ [K,C]
    gemm_bf16x3_kernel<<<dim3(C_ / GBN, M / GBM), 256, GEMM_SMEM_BYTES>>>(
        a2, bt2, out, M, C_, K);
}